// round 12
// baseline (speedup 1.0000x reference)
#include <cuda_runtime.h>
#include <cstdint>

typedef unsigned long long ull;

#define Bb 256
#define Ss 365
#define FDd 32
#define FSs 27
#define Hh 256
#define KK 288              // 32 (x) + 256 (h) combined reduction dim
#define KP 144              // k-pairs
#define NTHR 384
#define NWARP 12
#define KPW 12              // k-pairs per warp
#define OFF_H 93440         // out: [B*S] floats first
#define OFF_C 24014080      // then h_n [B,S,H], then c_n [B,S,H]

// smem layout (bytes)
#define HPB 18432                        // one hp2 buffer: [8 bpairs][288 k] f32x2
#define SMEM_HP   0                      // 2 buffers = 36864
#define SMEM_PART 36864                  // [12 ksplit][8 bp][3 g][32 j] f32x2 = 73728
#define SMEM_MBAR 110592                 // 2 mbarriers
#define SMEM_TOTAL 110720
#define NARRIVE 68                       // 8 CTAs x 8 state warps + 4 local x warps

__device__ __forceinline__ ull dupf(float x) {
    ull d; asm("mov.b64 %0, {%1, %1};" : "=l"(d) : "f"(x)); return d;
}
__device__ __forceinline__ ull packf(float lo, float hi) {
    ull d; asm("mov.b64 %0, {%1, %2};" : "=l"(d) : "f"(lo), "f"(hi)); return d;
}
__device__ __forceinline__ void unpackf(ull v, float& lo, float& hi) {
    asm("mov.b64 {%0, %1}, %2;" : "=f"(lo), "=f"(hi) : "l"(v));
}
__device__ __forceinline__ void unpack_dup(ull v, ull& d0, ull& d1) {
    float lo, hi;
    asm("mov.b64 {%0, %1}, %2;" : "=f"(lo), "=f"(hi) : "l"(v));
    d0 = dupf(lo);
    d1 = dupf(hi);
}
__device__ __forceinline__ void fma2(ull& d, ull a, ull b) {
    asm("fma.rn.f32x2 %0, %1, %2, %0;" : "+l"(d) : "l"(a), "l"(b));
}
__device__ __forceinline__ ull add2(ull a, ull b) {
    ull d; asm("add.rn.f32x2 %0, %1, %2;" : "=l"(d) : "l"(a), "l"(b)); return d;
}
__device__ __forceinline__ float sigm(float x) {
    x = fminf(fmaxf(x, -30.f), 30.f);
    return __fdividef(1.f, 1.f + __expf(-x));
}
__device__ __forceinline__ float tanh_(float x) {
    float ax = fminf(fabsf(x), 15.f);
    float e = __expf(2.f * ax);
    float r = 1.f - __fdividef(2.f, e + 1.f);
    return copysignf(r, x);
}
__device__ __forceinline__ uint32_t smem_u32_of(const void* p) {
    uint32_t a;
    asm("{ .reg .u64 t; cvta.to.shared.u64 t, %1; cvt.u32.u64 %0, t; }"
        : "=r"(a) : "l"(p));
    return a;
}
// DSMEM store: write 8B into CTA `rank`'s smem at the same local offset
__device__ __forceinline__ void st_cluster_u64(uint32_t laddr, uint32_t rank, ull v) {
    asm volatile(
        "{\n\t.reg .b32 r;\n\t"
        "mapa.shared::cluster.u32 r, %0, %1;\n\t"
        "st.shared::cluster.b64 [r], %2;\n\t}"
        :: "r"(laddr), "r"(rank), "l"(v) : "memory");
}
// remote mbarrier arrive (release, cluster scope)
__device__ __forceinline__ void mbar_arrive_rank(uint32_t lmbar, uint32_t rank) {
    asm volatile(
        "{\n\t.reg .b32 r;\n\t"
        "mapa.shared::cluster.u32 r, %0, %1;\n\t"
        "mbarrier.arrive.release.cluster.shared::cluster.b64 _, [r];\n\t}"
        :: "r"(lmbar), "r"(rank) : "memory");
}
// local mbarrier arrive with cluster-release semantics
__device__ __forceinline__ void mbar_arrive_local(uint32_t lmbar) {
    asm volatile(
        "mbarrier.arrive.release.cluster.shared::cta.b64 _, [%0];"
        :: "r"(lmbar) : "memory");
}
#define MBAR_INIT(addr, cnt) \
    asm volatile("mbarrier.init.shared.b64 [%0], %1;" :: "r"(addr), "r"(cnt) : "memory")
#define MBAR_WAIT_CL(mbar, par) do { \
    asm volatile( \
        "{\n\t.reg .pred P1;\n\t" \
        "WAIT_%=:\n\t" \
        "mbarrier.try_wait.parity.acquire.cluster.shared::cta.b64 P1, [%0], %1, 0x989680;\n\t" \
        "@P1 bra.uni DONE_%=;\n\t" \
        "bra.uni WAIT_%=;\n\t" \
        "DONE_%=:\n\t}" \
        :: "r"(mbar), "r"(par) : "memory"); \
} while (0)
#define CLUSTER_SYNC_() do { \
    asm volatile("barrier.cluster.arrive.aligned;" ::: "memory"); \
    asm volatile("barrier.cluster.wait.aligned;" ::: "memory"); \
} while (0)

__global__ void __cluster_dims__(8, 1, 1) __launch_bounds__(NTHR, 1)
ealstm_seg(const float* __restrict__ x_d, const float* __restrict__ x_s,
           const float* __restrict__ W_ih, const float* __restrict__ W_hh,
           const float* __restrict__ W_sh, const float* __restrict__ bias,
           const float* __restrict__ bias_s, float* __restrict__ out,
           int t0, int t1)
{
    extern __shared__ char smem[];
    ull* part = (ull*)(smem + SMEM_PART);                         // [12][8][3][32]
    const uint32_t smem_b = smem_u32_of(smem);
    const uint32_t mb0 = smem_b + SMEM_MBAR;

    const int tid = threadIdx.x;
    const int cl  = blockIdx.x >> 3;     // 16 clusters
    const int b0  = cl * 16;             // 16 batch rows per cluster
    const int rk  = blockIdx.x & 7;      // rank in cluster
    const int h0  = rk * 32;             // 32 hidden cols per CTA
    const int w   = tid >> 5;            // warp 0..11 = k-split id
    const int lane = tid & 31;           // = j within slice

    // ---- mbarrier init + cluster sync (remote stores must come after peer init) ----
    if (tid == 0) {
        MBAR_INIT(mb0, NARRIVE);
        MBAR_INIT(mb0 + 8, NARRIVE);
    }
    __syncthreads();
    CLUSTER_SYNC_();

    // ---- prologue: W slice into REGISTERS, k-pair packed ----
    ull wreg[KPW * 3];
    #pragma unroll
    for (int i = 0; i < KPW; i++) {
        const int k0 = (w * KPW + i) * 2;
        #pragma unroll
        for (int g = 0; g < 3; g++) {
            const int col = g * 256 + h0 + lane;
            float v0, v1;
            if (k0 < 32) {
                v0 = W_ih[k0 * 768 + col];
                v1 = W_ih[(k0 + 1) * 768 + col];
            } else {
                v0 = W_hh[(k0 - 32) * 768 + col];
                v1 = W_hh[(k0 - 31) * 768 + col];
            }
            wreg[i * 3 + g] = packf(v0, v1);
        }
    }

    // state warps 0-7: thread (w, lane) owns rows (b0+w, b0+w+8), col h0+lane
    const int jg = h0 + lane;
    float igv[2], cst[2];
    ull bfd = 0, bod = 0, bgd = 0;
    if (w < 8) {
        #pragma unroll
        for (int e = 0; e < 2; e++) {
            int b = b0 + w + 8 * e;
            float a = bias_s[jg];
            #pragma unroll
            for (int k = 0; k < FSs; k++)
                a = fmaf(x_s[b * FSs + k], W_sh[k * Hh + jg], a);
            igv[e] = sigm(a);
            cst[e] = (t0 == 0) ? 0.f
                               : __ldcg(&out[OFF_C + (b * Ss + (t0 - 1)) * Hh + jg]);
        }
        bfd = dupf(bias[jg]);
        bod = dupf(bias[256 + jg]);
        bgd = dupf(bias[512 + jg]);
        // push h[t0-1] slice (or zeros) into ALL CTAs' buffer 0
        ull hpk = 0ull;
        if (t0 > 0) {
            float lo = __ldcg(&out[OFF_H + ((b0 + w) * Ss + (t0 - 1)) * Hh + jg]);
            float hi = __ldcg(&out[OFF_H + ((b0 + w + 8) * Ss + (t0 - 1)) * Hh + jg]);
            hpk = packf(lo, hi);
        }
        uint32_t dst = smem_b + SMEM_HP + (uint32_t)(w * KK + 32 + jg) * 8u;
        #pragma unroll
        for (uint32_t r = 0; r < 8; r++) st_cluster_u64(dst, r, hpk);
        if (lane == 0) {
            #pragma unroll
            for (uint32_t r = 0; r < 8; r++) mbar_arrive_rank(mb0, r);
        }
    } else {
        // x warps 8-11: stage x_{t0} into buffer 0 (local)
        const int q = w - 8;
        ull* hp0 = (ull*)(smem + SMEM_HP);
        #pragma unroll
        for (int e = 0; e < 2; e++) {
            int bp = q * 2 + e;
            float lo = x_d[((b0 + bp) * Ss + t0) * FDd + lane];
            float hi = x_d[((b0 + bp + 8) * Ss + t0) * FDd + lane];
            hp0[bp * KK + lane] = packf(lo, hi);
        }
        if (lane == 0) mbar_arrive_local(mb0);
    }

    for (int t = t0; t < t1; t++) {
        const int dt = t - t0;
        const int bi = dt & 1;
        const int par = ((dt - bi) >> 1) & 1;
        // wait until all 8 CTAs' h slices + local x are in buffer bi
        MBAR_WAIT_CL(mb0 + bi * 8, par);

        // ---- GEMM: warp w does k-pairs [w*12, w*12+12), all 8 bpairs, W in regs ----
        const ulonglong2* hv2 = (const ulonglong2*)(smem + SMEM_HP + bi * HPB);
        ull acc[24];
        #pragma unroll
        for (int i = 0; i < 24; i++) acc[i] = 0ull;
        #pragma unroll
        for (int i = 0; i < KPW; i++) {
            const int kp = w * KPW + i;
            ull d0, d1, d2, d3, d4, d5;
            unpack_dup(wreg[i * 3 + 0], d0, d1);
            unpack_dup(wreg[i * 3 + 1], d2, d3);
            unpack_dup(wreg[i * 3 + 2], d4, d5);
            #pragma unroll
            for (int bp = 0; bp < 8; bp++) {
                ulonglong2 h2 = hv2[bp * KP + kp];       // broadcast LDS.128
                fma2(acc[bp * 3 + 0], h2.x, d0);
                fma2(acc[bp * 3 + 1], h2.x, d2);
                fma2(acc[bp * 3 + 2], h2.x, d4);
                fma2(acc[bp * 3 + 0], h2.y, d1);
                fma2(acc[bp * 3 + 1], h2.y, d3);
                fma2(acc[bp * 3 + 2], h2.y, d5);
            }
        }
        #pragma unroll
        for (int bp = 0; bp < 8; bp++)
            #pragma unroll
            for (int g = 0; g < 3; g++)
                part[((w * 8 + bp) * 3 + g) * 32 + lane] = acc[bp * 3 + g];
        __syncthreads();   // also fences all buffer-bi reads before peers may overwrite

        if (w < 8) {
            // ---- tree-reduce 12 K-splits + bias ----
            ull s[3];
            #pragma unroll
            for (int g = 0; g < 3; g++) {
                ull p[NWARP];
                #pragma unroll
                for (int wk = 0; wk < NWARP; wk++)
                    p[wk] = part[((wk * 8 + w) * 3 + g) * 32 + lane];
                ull a0 = add2(add2(p[0], p[1]), add2(p[2], p[3]));
                ull a1 = add2(add2(p[4], p[5]), add2(p[6], p[7]));
                ull a2 = add2(add2(p[8], p[9]), add2(p[10], p[11]));
                s[g] = add2(add2(a0, a1), a2);
            }
            ull sf = add2(s[0], bfd), so = add2(s[1], bod), sg = add2(s[2], bgd);
            float f0, f1, o0, o1, g0, g1;
            unpackf(sf, f0, f1);
            unpackf(so, o0, o1);
            unpackf(sg, g0, g1);

            // ---- elementwise update ----
            cst[0] = sigm(f0) * cst[0] + igv[0] * tanh_(g0);
            float hv0 = sigm(o0) * tanh_(cst[0]);
            cst[1] = sigm(f1) * cst[1] + igv[1] * tanh_(g1);
            float hv1 = sigm(o1) * tanh_(cst[1]);

            // push packed h into ALL CTAs' buffer bi^1, then arrive (release)
            if (t + 1 < t1) {
                ull hpk = packf(hv0, hv1);
                uint32_t dst = smem_b + SMEM_HP + (uint32_t)(bi ^ 1) * HPB
                             + (uint32_t)(w * KK + 32 + jg) * 8u;
                #pragma unroll
                for (uint32_t r = 0; r < 8; r++) st_cluster_u64(dst, r, hpk);
                if (lane == 0) {
                    #pragma unroll
                    for (uint32_t r = 0; r < 8; r++)
                        mbar_arrive_rank(mb0 + (bi ^ 1) * 8, r);
                }
            }

            // h/c stores to out (off the critical path)
            int base0 = ((b0 + w) * Ss + t) * Hh + jg;
            int base1 = ((b0 + w + 8) * Ss + t) * Hh + jg;
            __stcg(&out[OFF_H + base0], hv0);
            __stcg(&out[OFF_C + base0], cst[0]);
            __stcg(&out[OFF_H + base1], hv1);
            __stcg(&out[OFF_C + base1], cst[1]);
        } else if (t + 1 < t1) {
            // x warps: stage x_{t+1} into buffer bi^1 during the reduce tail
            const int q = w - 8;
            ull* hpn = (ull*)(smem + SMEM_HP + (bi ^ 1) * HPB);
            #pragma unroll
            for (int e = 0; e < 2; e++) {
                int bp = q * 2 + e;
                float lo = x_d[((b0 + bp) * Ss + t + 1) * FDd + lane];
                float hi = x_d[((b0 + bp + 8) * Ss + t + 1) * FDd + lane];
                hpn[bp * KK + lane] = packf(lo, hi);
            }
            if (lane == 0) mbar_arrive_local(mb0 + (bi ^ 1) * 8);
        }
    }

    // keep cluster smem alive until all CTAs are past their last remote ops
    CLUSTER_SYNC_();
}

__global__ void __launch_bounds__(256)
fc_head(const float* __restrict__ h, const float* __restrict__ W_fc,
        const float* __restrict__ b_fc, float* __restrict__ outp)
{
    int row = blockIdx.x * 8 + (threadIdx.x >> 5);
    int lane = threadIdx.x & 31;
    if (row >= Bb * Ss) return;
    const float* hr = h + (size_t)row * Hh;
    float a = 0.f;
    #pragma unroll
    for (int i = 0; i < 8; i++)
        a = fmaf(hr[lane + 32 * i], W_fc[lane + 32 * i], a);
    #pragma unroll
    for (int s2 = 16; s2; s2 >>= 1)
        a += __shfl_xor_sync(0xffffffffu, a, s2);
    if (lane == 0) outp[row] = a + b_fc[0];
}

extern "C" void kernel_launch(void* const* d_in, const int* in_sizes, int n_in,
                              void* d_out, int out_size) {
    const float* x_d    = (const float*)d_in[0];
    const float* x_s    = (const float*)d_in[1];
    const float* W_ih   = (const float*)d_in[2];
    const float* W_hh   = (const float*)d_in[3];
    const float* W_sh   = (const float*)d_in[4];
    const float* bias   = (const float*)d_in[5];
    const float* bias_s = (const float*)d_in[6];
    const float* W_fc   = (const float*)d_in[7];
    const float* b_fc   = (const float*)d_in[8];
    float* out = (float*)d_out;

    cudaFuncSetAttribute(ealstm_seg, cudaFuncAttributeMaxDynamicSharedMemorySize, SMEM_TOTAL);
    // 6 segments: launches 0-5 are recurrence segments -> ncu -s 5 lands on steady state
    ealstm_seg<<<128, NTHR, SMEM_TOTAL>>>(x_d, x_s, W_ih, W_hh, W_sh, bias, bias_s, out, 0, 61);
    ealstm_seg<<<128, NTHR, SMEM_TOTAL>>>(x_d, x_s, W_ih, W_hh, W_sh, bias, bias_s, out, 61, 122);
    ealstm_seg<<<128, NTHR, SMEM_TOTAL>>>(x_d, x_s, W_ih, W_hh, W_sh, bias, bias_s, out, 122, 183);
    ealstm_seg<<<128, NTHR, SMEM_TOTAL>>>(x_d, x_s, W_ih, W_hh, W_sh, bias, bias_s, out, 183, 244);
    ealstm_seg<<<128, NTHR, SMEM_TOTAL>>>(x_d, x_s, W_ih, W_hh, W_sh, bias, bias_s, out, 244, 305);
    ealstm_seg<<<128, NTHR, SMEM_TOTAL>>>(x_d, x_s, W_ih, W_hh, W_sh, bias, bias_s, out, 305, 365);
    fc_head<<<(Bb * Ss + 7) / 8, 256>>>(out + OFF_H, W_fc, b_fc, out);
}

// round 13
// speedup vs baseline: 1.2386x; 1.2386x over previous
#include <cuda_runtime.h>
#include <cstdint>

typedef unsigned long long ull;

#define Bb 256
#define Ss 365
#define FDd 32
#define FSs 27
#define Hh 256
#define KK 288              // 32 (x) + 256 (h) combined reduction dim
#define KP 144              // k-pairs
#define NTHR 384
#define NWARP 12
#define KPW 12              // k-pairs per warp
#define OFF_H 93440         // out: [B*S] floats first
#define OFF_C 24014080      // then h_n [B,S,H], then c_n [B,S,H]

// smem layout (bytes)
#define SMEM_HP   0                      // [8 bpairs][288 k] f32x2 = 18432
#define SMEM_PART 18432                  // [12 ksplit][8 bp][3 g][32 j] f32x2 = 73728
#define SMEM_TOTAL 92160

// packed h exchange: [cluster][bpair][k-col] f32x2 (L2-resident, rewritten every step)
__device__ ull g_hx[16][8][256];

__device__ __forceinline__ ull dupf(float x) {
    ull d; asm("mov.b64 %0, {%1, %1};" : "=l"(d) : "f"(x)); return d;
}
__device__ __forceinline__ ull packf(float lo, float hi) {
    ull d; asm("mov.b64 %0, {%1, %2};" : "=l"(d) : "f"(lo), "f"(hi)); return d;
}
__device__ __forceinline__ void unpackf(ull v, float& lo, float& hi) {
    asm("mov.b64 {%0, %1}, %2;" : "=f"(lo), "=f"(hi) : "l"(v));
}
__device__ __forceinline__ void unpack_dup(ull v, ull& d0, ull& d1) {
    float lo, hi;
    asm("mov.b64 {%0, %1}, %2;" : "=f"(lo), "=f"(hi) : "l"(v));
    d0 = dupf(lo);
    d1 = dupf(hi);
}
__device__ __forceinline__ void fma2(ull& d, ull a, ull b) {
    asm("fma.rn.f32x2 %0, %1, %2, %0;" : "+l"(d) : "l"(a), "l"(b));
}
__device__ __forceinline__ ull add2(ull a, ull b) {
    ull d; asm("add.rn.f32x2 %0, %1, %2;" : "=l"(d) : "l"(a), "l"(b)); return d;
}
__device__ __forceinline__ float sigm(float x) {
    x = fminf(fmaxf(x, -30.f), 30.f);
    return __fdividef(1.f, 1.f + __expf(-x));
}
__device__ __forceinline__ float tanh_(float x) {
    float ax = fminf(fabsf(x), 15.f);
    float e = __expf(2.f * ax);
    float r = 1.f - __fdividef(2.f, e + 1.f);
    return copysignf(r, x);
}

__global__ void __cluster_dims__(8, 1, 1) __launch_bounds__(NTHR, 1)
ealstm_seg(const float* __restrict__ x_d, const float* __restrict__ x_s,
           const float* __restrict__ W_ih, const float* __restrict__ W_hh,
           const float* __restrict__ W_sh, const float* __restrict__ bias,
           const float* __restrict__ bias_s, float* __restrict__ out,
           int t0, int t1)
{
    extern __shared__ char smem[];
    ull* hp2 = (ull*)(smem + SMEM_HP);                            // [8][288]
    const ulonglong2* hv2 = (const ulonglong2*)(smem + SMEM_HP);  // [8][144]
    ull* part = (ull*)(smem + SMEM_PART);                         // [12][8][3][32]

    const int tid = threadIdx.x;
    const int cl  = blockIdx.x >> 3;     // 16 clusters
    const int b0  = cl * 16;             // 16 batch rows per cluster
    const int rk  = blockIdx.x & 7;      // rank in cluster
    const int h0  = rk * 32;             // 32 hidden cols per CTA
    const int w   = tid >> 5;            // warp 0..11 = k-split id
    const int lane = tid & 31;           // = j within slice

    // ---- prologue: W slice into REGISTERS, k-pair packed ----
    ull wreg[KPW * 3];
    #pragma unroll
    for (int i = 0; i < KPW; i++) {
        const int k0 = (w * KPW + i) * 2;
        #pragma unroll
        for (int g = 0; g < 3; g++) {
            const int col = g * 256 + h0 + lane;
            float v0, v1;
            if (k0 < 32) {
                v0 = W_ih[k0 * 768 + col];
                v1 = W_ih[(k0 + 1) * 768 + col];
            } else {
                v0 = W_hh[(k0 - 32) * 768 + col];
                v1 = W_hh[(k0 - 31) * 768 + col];
            }
            wreg[i * 3 + g] = packf(v0, v1);
        }
    }

    // state warps 0-7: thread (w, lane) owns rows (b0+w, b0+w+8), col h0+lane
    const int jg = h0 + lane;
    float igv[2], cst[2];
    ull bfd = 0, bod = 0, bgd = 0;
    if (w < 8) {
        #pragma unroll
        for (int e = 0; e < 2; e++) {
            int b = b0 + w + 8 * e;
            float a = bias_s[jg];
            #pragma unroll
            for (int k = 0; k < FSs; k++)
                a = fmaf(x_s[b * FSs + k], W_sh[k * Hh + jg], a);
            igv[e] = sigm(a);
            // resume cell state: exact value stored by the previous segment
            cst[e] = (t0 == 0) ? 0.f
                               : __ldcg(&out[OFF_C + (b * Ss + (t0 - 1)) * Hh + jg]);
        }
        bfd = dupf(bias[jg]);
        bod = dupf(bias[256 + jg]);
        bgd = dupf(bias[512 + jg]);
        // seed exchange tile for t0 (h_{t0-1}, zeros for t0==0)
        ull hpk = 0ull;
        if (t0 > 0) {
            float lo = __ldcg(&out[OFF_H + ((b0 + w) * Ss + (t0 - 1)) * Hh + jg]);
            float hi = __ldcg(&out[OFF_H + ((b0 + w + 8) * Ss + (t0 - 1)) * Hh + jg]);
            hpk = packf(lo, hi);
        }
        __stcg(&g_hx[cl][w][jg], hpk);
    } else {
        // warps 8-11: stage x_{t0} (warp 8+q handles bpairs 2q, 2q+1)
        const int q = w - 8;
        #pragma unroll
        for (int e = 0; e < 2; e++) {
            int bp = q * 2 + e;
            float lo = x_d[((b0 + bp) * Ss + t0) * FDd + lane];
            float hi = x_d[((b0 + bp + 8) * Ss + t0) * FDd + lane];
            hp2[bp * KK + lane] = packf(lo, hi);
        }
    }
    // order seed stores before any peer reads them
    asm volatile("barrier.cluster.arrive.aligned;" ::: "memory");
    asm volatile("barrier.cluster.wait.aligned;" ::: "memory");

    for (int t = t0; t < t1; t++) {
        // ---- stage h_{t-1}: warps 0-7 copy pre-packed bpair tile from exchange ----
        if (w < 8) {
            const ulonglong2* src = (const ulonglong2*)&g_hx[cl][w][0];
            ulonglong2* dst = (ulonglong2*)&hp2[w * KK + 32];
            #pragma unroll
            for (int j = 0; j < 4; j++)
                dst[j * 32 + lane] = __ldcg(&src[j * 32 + lane]);
        }
        __syncthreads();

        // ---- GEMM: warp w does k-pairs [w*12, w*12+12), all 8 bpairs, W in regs ----
        ull acc[24];
        #pragma unroll
        for (int i = 0; i < 24; i++) acc[i] = 0ull;
        #pragma unroll
        for (int i = 0; i < KPW; i++) {
            const int kp = w * KPW + i;
            ull d0, d1, d2, d3, d4, d5;
            unpack_dup(wreg[i * 3 + 0], d0, d1);
            unpack_dup(wreg[i * 3 + 1], d2, d3);
            unpack_dup(wreg[i * 3 + 2], d4, d5);
            #pragma unroll
            for (int bp = 0; bp < 8; bp++) {
                ulonglong2 h2 = hv2[bp * KP + kp];       // broadcast LDS.128
                fma2(acc[bp * 3 + 0], h2.x, d0);
                fma2(acc[bp * 3 + 1], h2.x, d2);
                fma2(acc[bp * 3 + 2], h2.x, d4);
                fma2(acc[bp * 3 + 0], h2.y, d1);
                fma2(acc[bp * 3 + 1], h2.y, d3);
                fma2(acc[bp * 3 + 2], h2.y, d5);
            }
        }
        #pragma unroll
        for (int bp = 0; bp < 8; bp++)
            #pragma unroll
            for (int g = 0; g < 3; g++)
                part[((w * 8 + bp) * 3 + g) * 32 + lane] = acc[bp * 3 + g];
        __syncthreads();

        if (w < 8) {
            // ---- tree-reduce 12 K-splits + bias ----
            ull s[3];
            #pragma unroll
            for (int g = 0; g < 3; g++) {
                ull p[NWARP];
                #pragma unroll
                for (int wk = 0; wk < NWARP; wk++)
                    p[wk] = part[((wk * 8 + w) * 3 + g) * 32 + lane];
                ull a0 = add2(add2(p[0], p[1]), add2(p[2], p[3]));
                ull a1 = add2(add2(p[4], p[5]), add2(p[6], p[7]));
                ull a2 = add2(add2(p[8], p[9]), add2(p[10], p[11]));
                s[g] = add2(add2(a0, a1), a2);
            }
            ull sf = add2(s[0], bfd), so = add2(s[1], bod), sg = add2(s[2], bgd);
            float f0, f1, o0, o1, g0, g1;
            unpackf(sf, f0, f1);
            unpackf(so, o0, o1);
            unpackf(sg, g0, g1);

            // ---- elementwise update ----
            cst[0] = sigm(f0) * cst[0] + igv[0] * tanh_(g0);
            float hv0 = sigm(o0) * tanh_(cst[0]);
            cst[1] = sigm(f1) * cst[1] + igv[1] * tanh_(g1);
            float hv1 = sigm(o1) * tanh_(cst[1]);

            // exchange tile first (critical path), out stores after
            __stcg(&g_hx[cl][w][jg], packf(hv0, hv1));

            int base0 = ((b0 + w) * Ss + t) * Hh + jg;
            int base1 = ((b0 + w + 8) * Ss + t) * Hh + jg;
            __stcg(&out[OFF_H + base0], hv0);
            __stcg(&out[OFF_C + base0], cst[0]);
            __stcg(&out[OFF_H + base1], hv1);
            __stcg(&out[OFF_C + base1], cst[1]);
        } else if (t + 1 < t1) {
            // warps 8-11: stage x_{t+1} during the reduce/elementwise tail
            const int q = w - 8;
            #pragma unroll
            for (int e = 0; e < 2; e++) {
                int bp = q * 2 + e;
                float lo = x_d[((b0 + bp) * Ss + t + 1) * FDd + lane];
                float hi = x_d[((b0 + bp + 8) * Ss + t + 1) * FDd + lane];
                hp2[bp * KK + lane] = packf(lo, hi);
            }
        }

        // cluster barrier: release our exchange stores / acquire peers'
        asm volatile("barrier.cluster.arrive.aligned;" ::: "memory");
        asm volatile("barrier.cluster.wait.aligned;" ::: "memory");
    }
}

__global__ void __launch_bounds__(256)
fc_head(const float* __restrict__ h, const float* __restrict__ W_fc,
        const float* __restrict__ b_fc, float* __restrict__ outp)
{
    int row = blockIdx.x * 8 + (threadIdx.x >> 5);
    int lane = threadIdx.x & 31;
    if (row >= Bb * Ss) return;
    const float* hr = h + (size_t)row * Hh;
    float a = 0.f;
    #pragma unroll
    for (int i = 0; i < 8; i++)
        a = fmaf(hr[lane + 32 * i], W_fc[lane + 32 * i], a);
    #pragma unroll
    for (int s2 = 16; s2; s2 >>= 1)
        a += __shfl_xor_sync(0xffffffffu, a, s2);
    if (lane == 0) outp[row] = a + b_fc[0];
}

extern "C" void kernel_launch(void* const* d_in, const int* in_sizes, int n_in,
                              void* d_out, int out_size) {
    const float* x_d    = (const float*)d_in[0];
    const float* x_s    = (const float*)d_in[1];
    const float* W_ih   = (const float*)d_in[2];
    const float* W_hh   = (const float*)d_in[3];
    const float* W_sh   = (const float*)d_in[4];
    const float* bias   = (const float*)d_in[5];
    const float* bias_s = (const float*)d_in[6];
    const float* W_fc   = (const float*)d_in[7];
    const float* b_fc   = (const float*)d_in[8];
    float* out = (float*)d_out;

    cudaFuncSetAttribute(ealstm_seg, cudaFuncAttributeMaxDynamicSharedMemorySize, SMEM_TOTAL);
    // 3 segments: minimal launch/prologue overhead (measured ~29us per extra segment)
    ealstm_seg<<<128, NTHR, SMEM_TOTAL>>>(x_d, x_s, W_ih, W_hh, W_sh, bias, bias_s, out, 0, 122);
    ealstm_seg<<<128, NTHR, SMEM_TOTAL>>>(x_d, x_s, W_ih, W_hh, W_sh, bias, bias_s, out, 122, 244);
    ealstm_seg<<<128, NTHR, SMEM_TOTAL>>>(x_d, x_s, W_ih, W_hh, W_sh, bias, bias_s, out, 244, 365);
    fc_head<<<(Bb * Ss + 7) / 8, 256>>>(out + OFF_H, W_fc, b_fc, out);
}